// round 8
// baseline (speedup 1.0000x reference)
#include <cuda_runtime.h>
#include <cuda_bf16.h>
#include <cstdint>
#include <math.h>

#define BB 64
#define TT 1024
#define JJ 128
#define DD 256
#define TM 64    // t rows per CTA tile

// ---------------- device scratch ----------------
__device__ __align__(16) __nv_bfloat16 g_Uhi[BB * JJ * DD];
__device__ __align__(16) __nv_bfloat16 g_Ulo[BB * JJ * DD];
__device__ float g_su[BB * JJ];
__device__ float g_rowmax[BB * TT];
__device__ float g_q2c[BB * DD];

__device__ __forceinline__ void bsplit(float v, uint16_t& hi, uint16_t& lo) {
    __nv_bfloat16 h = __float2bfloat16(v);
    hi = __bfloat16_as_ushort(h);
    lo = __bfloat16_as_ushort(__float2bfloat16(v - __bfloat162float(h)));
}

__device__ __forceinline__ void mma16816(float* c, const uint32_t* a, const uint32_t* b) {
    asm volatile(
        "mma.sync.aligned.m16n8k16.row.col.f32.bf16.bf16.f32 "
        "{%0,%1,%2,%3}, {%4,%5,%6,%7}, {%8,%9}, {%0,%1,%2,%3};"
        : "+f"(c[0]), "+f"(c[1]), "+f"(c[2]), "+f"(c[3])
        : "r"(a[0]), "r"(a[1]), "r"(a[2]), "r"(a[3]), "r"(b[0]), "r"(b[1]));
}
__device__ __forceinline__ void ldsm4(uint32_t* r, uint32_t addr) {
    asm volatile("ldmatrix.sync.aligned.m8n8.x4.shared.b16 {%0,%1,%2,%3}, [%4];"
        : "=r"(r[0]), "=r"(r[1]), "=r"(r[2]), "=r"(r[3]) : "r"(addr));
}
__device__ __forceinline__ void ldsm4t(uint32_t* r, uint32_t addr) {
    asm volatile("ldmatrix.sync.aligned.m8n8.x4.trans.shared.b16 {%0,%1,%2,%3}, [%4];"
        : "=r"(r[0]), "=r"(r[1]), "=r"(r[2]), "=r"(r[3]) : "r"(addr));
}
#define CP_ASYNC16(dst, src) \
    asm volatile("cp.async.cg.shared.global [%0], [%1], 16;" :: "r"(dst), "l"(src))
#define CP_COMMIT() asm volatile("cp.async.commit_group;" ::: "memory")
#define CP_WAIT0()  asm volatile("cp.async.wait_group 0;" ::: "memory")

// ---------------- smem layout (bytes) ----------------
// SA: [64][136] bf16 (A chunk / probs), pitch 272B
// SB: [128][136] bf16 (U chunk), pitch 272B; epilogue f32 buffer overlays SB
#define SA_H 0u
#define SA_L 17408u
#define SB_H 34816u
#define SB_L 69632u
#define OFF_SSU 104448u   // [128] f32
#define OFF_SSH 104960u   // [64] f32
#define OFF_RM  105216u   // [64][4] f32
#define OFF_RS  106240u   // [64][4] f32
#define OFF_WHU 107264u   // [256] f32
#define OFF_WH  108288u   // [256] f32
#define SMEM_TOTAL 109312u

// ---------------- U split + su precompute (128 blocks) ----------------
__global__ void usplit_kernel(const float* __restrict__ U, const float* __restrict__ w_u) {
    __shared__ float sSu[64];
    int b = blockIdx.x >> 1, jh = blockIdx.x & 1;
    int tid = threadIdx.x, lane = tid & 31;
    float wu = w_u[tid];
    if (tid < 64) sSu[tid] = 0.f;
    __syncthreads();
    const float* Ub = U + (size_t)b * JJ * DD;
    __nv_bfloat16* uh = g_Uhi + (size_t)b * JJ * DD;
    __nv_bfloat16* ul = g_Ulo + (size_t)b * JJ * DD;
    for (int r = 0; r < 64; r++) {
        int j = jh * 64 + r;
        float v = Ub[j * DD + tid];
        uint16_t hi, lo; bsplit(v, hi, lo);
        uh[j * DD + tid] = __ushort_as_bfloat16(hi);
        ul[j * DD + tid] = __ushort_as_bfloat16(lo);
        float p = v * wu;
        #pragma unroll
        for (int o = 16; o; o >>= 1) p += __shfl_xor_sync(0xffffffffu, p, o);
        if (lane == 0) atomicAdd(&sSu[r], p);
    }
    __syncthreads();
    if (tid < 64) g_su[b * JJ + jh * 64 + tid] = sSu[tid];
}

// ---------------- main fused kernel ----------------
__global__ void __launch_bounds__(256, 2)
bidaf_main(const float* __restrict__ H, const float* __restrict__ w_h,
           const float* __restrict__ w_hu, float* __restrict__ G) {
    extern __shared__ char smem[];
    const uint32_t sbase = (uint32_t)__cvta_generic_to_shared(smem);
    const int b = blockIdx.y;
    const int t0 = blockIdx.x * TM;
    const int tid = threadIdx.x;
    const int wid = tid >> 5, lane = tid & 31;
    const int g = lane >> 2, qt = lane & 3;
    const int l16 = lane & 15, lh = lane >> 4;
    const int wm = wid >> 2, wn = wid & 3;   // 2x4 warp grid, both GEMMs

    float* sWhu = (float*)(smem + OFF_WHU);
    float* sWh  = (float*)(smem + OFF_WH);
    float* ssu  = (float*)(smem + OFF_SSU);
    float* ssh  = (float*)(smem + OFF_SSH);
    float* sRM  = (float*)(smem + OFF_RM);
    float* sRS  = (float*)(smem + OFF_RS);

    const char* UgH = (const char*)(g_Uhi + (size_t)b * JJ * DD);
    const char* UgL = (const char*)(g_Ulo + (size_t)b * JJ * DD);

    // helper: stage U chunk [128 j][128 d] hi/lo from column offset d0 (bytes 2*d0)
    auto stageU = [&](int d0) {
        #pragma unroll
        for (int k = 0; k < 8; k++) {
            int idx = tid + 256 * k;          // 2048 granules of 16B per buffer
            int j = idx >> 4, c = idx & 15;
            uint32_t dst = sbase + (uint32_t)(j * 272 + c * 16);
            const char* s = (const char*)(j * 512 + d0 * 2 + c * 16);
            CP_ASYNC16(dst + SB_H, UgH + (size_t)(uintptr_t)s);
            CP_ASYNC16(dst + SB_L, UgL + (size_t)(uintptr_t)s);
        }
        CP_COMMIT();
    };

    stageU(128);                 // GEMM1 first chunk: d[128:256]

    sWhu[tid] = w_hu[tid];
    sWh[tid]  = w_h[tid];
    if (tid < JJ) ssu[tid] = g_su[b * JJ + tid];

    float C1[2][4][4];
    #pragma unroll
    for (int mf = 0; mf < 2; mf++)
        #pragma unroll
        for (int nf = 0; nf < 4; nf++)
            #pragma unroll
            for (int q = 0; q < 4; q++) C1[mf][nf][q] = 0.f;
    float shreg[8];
    #pragma unroll
    for (int k = 0; k < 8; k++) shreg[k] = 0.f;

    __syncthreads();

    // ================= GEMM1: S[64t][128j], K=256, chunk order {1,0} =================
    #pragma unroll
    for (int cc = 0; cc < 2; cc++) {
        const int d0 = (cc == 0) ? 128 : 0;
        // --- stage A chunk = H*w_hu hi/lo [64][128] ---
        {
            const float4* H4 = (const float4*)(H + ((size_t)(b * TT + t0)) * DD);
            #pragma unroll
            for (int k = 0; k < 8; k++) {
                int row = 8 * k + wid;
                int d = d0 + lane * 4;
                float4 v = H4[row * 64 + (d >> 2)];
                float a0 = v.x * sWhu[d],     a1 = v.y * sWhu[d + 1];
                float a2 = v.z * sWhu[d + 2], a3 = v.w * sWhu[d + 3];
                uint16_t h0,l0,h1,l1,h2,l2,h3,l3;
                bsplit(a0,h0,l0); bsplit(a1,h1,l1); bsplit(a2,h2,l2); bsplit(a3,h3,l3);
                uint32_t off = (uint32_t)row * 272u + (uint32_t)lane * 8u;
                *(uint2*)(smem + SA_H + off) = make_uint2((uint32_t)h0 | ((uint32_t)h1 << 16),
                                                          (uint32_t)h2 | ((uint32_t)h3 << 16));
                *(uint2*)(smem + SA_L + off) = make_uint2((uint32_t)l0 | ((uint32_t)l1 << 16),
                                                          (uint32_t)l2 | ((uint32_t)l3 << 16));
                float sh = v.x * sWh[d] + v.y * sWh[d + 1] + v.z * sWh[d + 2] + v.w * sWh[d + 3];
                #pragma unroll
                for (int o = 16; o; o >>= 1) sh += __shfl_xor_sync(0xffffffffu, sh, o);
                shreg[k] += sh;
            }
        }
        CP_WAIT0();
        __syncthreads();

        #pragma unroll
        for (int ks = 0; ks < 8; ks++) {
            uint32_t aH[2][4], aL[2][4];
            #pragma unroll
            for (int mf = 0; mf < 2; mf++) {
                uint32_t ar = sbase + (uint32_t)((wm * 32 + mf * 16 + l16) * 272 + ks * 32 + lh * 16);
                ldsm4(aH[mf], ar + SA_H);
                ldsm4(aL[mf], ar + SA_L);
            }
            #pragma unroll
            for (int p = 0; p < 2; p++) {
                uint32_t br = sbase + (uint32_t)((wn * 32 + p * 16 + l16) * 272 + ks * 32 + lh * 16);
                uint32_t bh[4], bl[4];
                ldsm4(bh, br + SB_H);
                ldsm4(bl, br + SB_L);
                uint32_t B0h[2] = {bh[0], bh[2]}, B1h[2] = {bh[1], bh[3]};
                uint32_t B0l[2] = {bl[0], bl[2]}, B1l[2] = {bl[1], bl[3]};
                #pragma unroll
                for (int mf = 0; mf < 2; mf++) {
                    mma16816(C1[mf][2*p],   aH[mf], B0h);
                    mma16816(C1[mf][2*p],   aL[mf], B0h);
                    mma16816(C1[mf][2*p],   aH[mf], B0l);
                    mma16816(C1[mf][2*p+1], aH[mf], B1h);
                    mma16816(C1[mf][2*p+1], aL[mf], B1h);
                    mma16816(C1[mf][2*p+1], aH[mf], B1l);
                }
            }
        }
        __syncthreads();
        if (cc == 0) stageU(0);   // GEMM1 chunk 0 (= GEMM2 half 0, stays resident)
    }
    if (lane == 0) {
        #pragma unroll
        for (int k = 0; k < 8; k++) ssh[8 * k + wid] = shreg[k];
    }

    // ================= softmax over j =================
    #pragma unroll
    for (int mf = 0; mf < 2; mf++) {
        int r0 = wm * 32 + mf * 16 + g;
        float m0 = -1e30f, m1 = -1e30f;
        #pragma unroll
        for (int nf = 0; nf < 4; nf++) {
            float2 su2 = *(const float2*)&ssu[wn * 32 + nf * 8 + qt * 2];
            C1[mf][nf][0] += su2.x; C1[mf][nf][1] += su2.y;
            C1[mf][nf][2] += su2.x; C1[mf][nf][3] += su2.y;
            m0 = fmaxf(m0, fmaxf(C1[mf][nf][0], C1[mf][nf][1]));
            m1 = fmaxf(m1, fmaxf(C1[mf][nf][2], C1[mf][nf][3]));
        }
        #pragma unroll
        for (int o = 1; o < 4; o <<= 1) {
            m0 = fmaxf(m0, __shfl_xor_sync(0xffffffffu, m0, o));
            m1 = fmaxf(m1, __shfl_xor_sync(0xffffffffu, m1, o));
        }
        if (qt == 0) { sRM[r0 * 4 + wn] = m0; sRM[(r0 + 8) * 4 + wn] = m1; }
    }
    __syncthreads();
    #pragma unroll
    for (int mf = 0; mf < 2; mf++) {
        int r0 = wm * 32 + mf * 16 + g;
        float M0 = fmaxf(fmaxf(sRM[r0*4], sRM[r0*4+1]), fmaxf(sRM[r0*4+2], sRM[r0*4+3]));
        float M1 = fmaxf(fmaxf(sRM[(r0+8)*4], sRM[(r0+8)*4+1]),
                         fmaxf(sRM[(r0+8)*4+2], sRM[(r0+8)*4+3]));
        float s0 = 0.f, s1 = 0.f;
        #pragma unroll
        for (int nf = 0; nf < 4; nf++) {
            C1[mf][nf][0] = __expf(C1[mf][nf][0] - M0);
            C1[mf][nf][1] = __expf(C1[mf][nf][1] - M0);
            C1[mf][nf][2] = __expf(C1[mf][nf][2] - M1);
            C1[mf][nf][3] = __expf(C1[mf][nf][3] - M1);
            s0 += C1[mf][nf][0] + C1[mf][nf][1];
            s1 += C1[mf][nf][2] + C1[mf][nf][3];
        }
        #pragma unroll
        for (int o = 1; o < 4; o <<= 1) {
            s0 += __shfl_xor_sync(0xffffffffu, s0, o);
            s1 += __shfl_xor_sync(0xffffffffu, s1, o);
        }
        if (qt == 0) {
            sRS[r0 * 4 + wn] = s0; sRS[(r0 + 8) * 4 + wn] = s1;
            if (wn == 0) {
                g_rowmax[b * TT + t0 + r0]     = M0 + ssh[r0];
                g_rowmax[b * TT + t0 + r0 + 8] = M1 + ssh[r0 + 8];
            }
        }
    }
    __syncthreads();
    // normalize + pack probs bf16 hi/lo into SA ([64 t][128 j])
    #pragma unroll
    for (int mf = 0; mf < 2; mf++) {
        int r0 = wm * 32 + mf * 16 + g;
        float inv0 = 1.f / (sRS[r0*4] + sRS[r0*4+1] + sRS[r0*4+2] + sRS[r0*4+3]);
        float inv1 = 1.f / (sRS[(r0+8)*4] + sRS[(r0+8)*4+1] + sRS[(r0+8)*4+2] + sRS[(r0+8)*4+3]);
        #pragma unroll
        for (int nf = 0; nf < 4; nf++) {
            int col = wn * 32 + nf * 8 + qt * 2;
            float p00 = C1[mf][nf][0] * inv0, p01 = C1[mf][nf][1] * inv0;
            float p10 = C1[mf][nf][2] * inv1, p11 = C1[mf][nf][3] * inv1;
            uint16_t h0,l0,h1,l1,h2,l2,h3,l3;
            bsplit(p00,h0,l0); bsplit(p01,h1,l1); bsplit(p10,h2,l2); bsplit(p11,h3,l3);
            uint32_t o0 = (uint32_t)r0 * 272u + (uint32_t)col * 2u;
            uint32_t o1 = (uint32_t)(r0 + 8) * 272u + (uint32_t)col * 2u;
            *(uint32_t*)(smem + SA_H + o0) = (uint32_t)h0 | ((uint32_t)h1 << 16);
            *(uint32_t*)(smem + SA_L + o0) = (uint32_t)l0 | ((uint32_t)l1 << 16);
            *(uint32_t*)(smem + SA_H + o1) = (uint32_t)h2 | ((uint32_t)h3 << 16);
            *(uint32_t*)(smem + SA_L + o1) = (uint32_t)l2 | ((uint32_t)l3 << 16);
        }
    }
    CP_WAIT0();          // U half 0 resident
    __syncthreads();

    // ================= GEMM2 (two d-halves): C2Q = P @ U =================
    #pragma unroll
    for (int hf = 0; hf < 2; hf++) {
        float C2[2][4][4];
        #pragma unroll
        for (int mf = 0; mf < 2; mf++)
            #pragma unroll
            for (int nf = 0; nf < 4; nf++)
                #pragma unroll
                for (int q = 0; q < 4; q++) C2[mf][nf][q] = 0.f;

        #pragma unroll
        for (int ks = 0; ks < 8; ks++) {
            uint32_t aH[2][4], aL[2][4];
            #pragma unroll
            for (int mf = 0; mf < 2; mf++) {
                uint32_t ar = sbase + (uint32_t)((wm * 32 + mf * 16 + l16) * 272 + ks * 32 + lh * 16);
                ldsm4(aH[mf], ar + SA_H);
                ldsm4(aL[mf], ar + SA_L);
            }
            #pragma unroll
            for (int p = 0; p < 2; p++) {
                uint32_t br = sbase + (uint32_t)((ks * 16 + l16) * 272
                                                 + (wn * 32 + p * 16 + lh * 8) * 2);
                uint32_t bh[4], bl[4];
                ldsm4t(bh, br + SB_H);
                ldsm4t(bl, br + SB_L);
                uint32_t B0h[2] = {bh[0], bh[1]}, B1h[2] = {bh[2], bh[3]};
                uint32_t B0l[2] = {bl[0], bl[1]}, B1l[2] = {bl[2], bl[3]};
                #pragma unroll
                for (int mf = 0; mf < 2; mf++) {
                    mma16816(C2[mf][2*p],   aH[mf], B0h);
                    mma16816(C2[mf][2*p],   aL[mf], B0h);
                    mma16816(C2[mf][2*p],   aH[mf], B0l);
                    mma16816(C2[mf][2*p+1], aH[mf], B1h);
                    mma16816(C2[mf][2*p+1], aL[mf], B1h);
                    mma16816(C2[mf][2*p+1], aH[mf], B1l);
                }
            }
        }
        __syncthreads();   // U half dead -> overlay epilogue buffer

        // ---- epilogue for this half: sEpi [64][132] f32 overlays SB ----
        {
            float* sEpi = (float*)(smem + SB_H);
            #pragma unroll
            for (int mf = 0; mf < 2; mf++) {
                int r0 = wm * 32 + mf * 16 + g;
                #pragma unroll
                for (int nf = 0; nf < 4; nf++) {
                    int c0 = wn * 32 + nf * 8 + qt * 2;
                    *(float2*)&sEpi[r0 * 132 + c0]       = make_float2(C2[mf][nf][0], C2[mf][nf][1]);
                    *(float2*)&sEpi[(r0 + 8) * 132 + c0] = make_float2(C2[mf][nf][2], C2[mf][nf][3]);
                }
            }
            __syncthreads();
            int row = tid >> 2, quad = tid & 3;
            size_t rowg = (size_t)(b * TT + t0 + row);
            const float* Hrow = H + rowg * DD + hf * 128;
            float* Grow = G + rowg * (4 * DD) + hf * 128;
            #pragma unroll
            for (int k = 0; k < 8; k++) {
                int dl = quad * 32 + k * 4;
                float4 cq = *(float4*)&sEpi[row * 132 + dl];
                float4 h = *(const float4*)&Hrow[dl];
                *(float4*)&Grow[dl] = h;
                *(float4*)&Grow[DD + dl] = cq;
                *(float4*)&Grow[2 * DD + dl] = make_float4(h.x*cq.x, h.y*cq.y, h.z*cq.z, h.w*cq.w);
            }
            __syncthreads();
        }
        if (hf == 0) {       // stage U half 1: d[128:256]
            stageU(128);
            CP_WAIT0();
            __syncthreads();
        }
    }
}

// ---------------- Q2C ----------------
__global__ void q2c_kernel(const float* __restrict__ H) {
    __shared__ float sb[TT];
    __shared__ float red[8];
    int b = blockIdx.x;
    int tid = threadIdx.x;
    int w = tid >> 5, lane = tid & 31;

    float v[4];
    float m = -1e30f;
    #pragma unroll
    for (int k = 0; k < 4; k++) { v[k] = g_rowmax[b * TT + tid + 256 * k]; m = fmaxf(m, v[k]); }
    #pragma unroll
    for (int o = 16; o; o >>= 1) m = fmaxf(m, __shfl_xor_sync(0xffffffffu, m, o));
    if (lane == 0) red[w] = m;
    __syncthreads();
    float M = red[0];
    #pragma unroll
    for (int i = 1; i < 8; i++) M = fmaxf(M, red[i]);
    __syncthreads();

    float sum = 0.f;
    #pragma unroll
    for (int k = 0; k < 4; k++) { float e = __expf(v[k] - M); sb[tid + 256 * k] = e; sum += e; }
    #pragma unroll
    for (int o = 16; o; o >>= 1) sum += __shfl_xor_sync(0xffffffffu, sum, o);
    if (lane == 0) red[w] = sum;
    __syncthreads();
    float S = 0.f;
    #pragma unroll
    for (int i = 0; i < 8; i++) S += red[i];
    float inv = 1.f / S;
    __syncthreads();

    const float* Hb = H + (size_t)b * TT * DD + tid;
    float q = 0.f;
    #pragma unroll 8
    for (int t = 0; t < TT; t++) q += sb[t] * Hb[(size_t)t * DD];
    g_q2c[b * DD + tid] = q * inv;
}

// ---------------- last quarter: G[:,3D:4D] = H * Q2C ----------------
__global__ void g3_kernel(const float* __restrict__ H, float* __restrict__ G) {
    size_t base = (size_t)blockIdx.x * 1024 + threadIdx.x;
    #pragma unroll
    for (int k = 0; k < 4; k++) {
        size_t idx = base + 256 * k;           // float4 units
        int d4 = (int)(idx & 63);
        size_t bt = idx >> 6;
        int b = (int)(bt >> 10);
        float4 h = ((const float4*)H)[idx];
        float4 q = ((const float4*)g_q2c)[b * 64 + d4];
        float4 o = make_float4(h.x * q.x, h.y * q.y, h.z * q.z, h.w * q.w);
        ((float4*)G)[bt * 256 + 192 + d4] = o;
    }
}

extern "C" void kernel_launch(void* const* d_in, const int* in_sizes, int n_in,
                              void* d_out, int out_size) {
    const float* H    = (const float*)d_in[0];
    const float* U    = (const float*)d_in[1];
    const float* w_h  = (const float*)d_in[2];
    const float* w_u  = (const float*)d_in[3];
    const float* w_hu = (const float*)d_in[4];
    float* G = (float*)d_out;

    cudaFuncSetAttribute(bidaf_main, cudaFuncAttributeMaxDynamicSharedMemorySize, SMEM_TOTAL);

    usplit_kernel<<<BB * 2, 256>>>(U, w_u);
    bidaf_main<<<dim3(TT / TM, BB), 256, SMEM_TOTAL>>>(H, w_h, w_hu, G);
    q2c_kernel<<<BB, 256>>>(H);
    g3_kernel<<<(BB * TT * DD / 4) / 1024, 256>>>(H, G);
}

// round 9
// speedup vs baseline: 1.0145x; 1.0145x over previous
#include <cuda_runtime.h>
#include <cuda_bf16.h>
#include <cstdint>
#include <math.h>

#define BB 64
#define TT 1024
#define JJ 128
#define DD 256
#define TM 128   // t rows per CTA tile

// ---------------- device scratch ----------------
__device__ __align__(16) __nv_bfloat16 g_Uhi[BB * JJ * DD];
__device__ __align__(16) __nv_bfloat16 g_Ulo[BB * JJ * DD];
__device__ __align__(16) __nv_bfloat16 g_Ahi[BB * TT * DD];
__device__ __align__(16) __nv_bfloat16 g_Alo[BB * TT * DD];
__device__ float g_su[BB * JJ];
__device__ float g_sh[BB * TT];
__device__ float g_rowmax[BB * TT];
__device__ float g_batt[BB * TT];
__device__ float g_q2cp[8 * BB * DD];
__device__ float g_q2c[BB * DD];

__device__ __forceinline__ void bsplit(float v, uint16_t& hi, uint16_t& lo) {
    __nv_bfloat16 h = __float2bfloat16(v);
    hi = __bfloat16_as_ushort(h);
    lo = __bfloat16_as_ushort(__float2bfloat16(v - __bfloat162float(h)));
}

__device__ __forceinline__ void mma16816(float* c, const uint32_t* a, const uint32_t* b) {
    asm volatile(
        "mma.sync.aligned.m16n8k16.row.col.f32.bf16.bf16.f32 "
        "{%0,%1,%2,%3}, {%4,%5,%6,%7}, {%8,%9}, {%0,%1,%2,%3};"
        : "+f"(c[0]), "+f"(c[1]), "+f"(c[2]), "+f"(c[3])
        : "r"(a[0]), "r"(a[1]), "r"(a[2]), "r"(a[3]), "r"(b[0]), "r"(b[1]));
}
__device__ __forceinline__ void ldsm4(uint32_t* r, uint32_t addr) {
    asm volatile("ldmatrix.sync.aligned.m8n8.x4.shared.b16 {%0,%1,%2,%3}, [%4];"
        : "=r"(r[0]), "=r"(r[1]), "=r"(r[2]), "=r"(r[3]) : "r"(addr));
}
__device__ __forceinline__ void ldsm4t(uint32_t* r, uint32_t addr) {
    asm volatile("ldmatrix.sync.aligned.m8n8.x4.trans.shared.b16 {%0,%1,%2,%3}, [%4];"
        : "=r"(r[0]), "=r"(r[1]), "=r"(r[2]), "=r"(r[3]) : "r"(addr));
}
#define CP_ASYNC16(dst, src) \
    asm volatile("cp.async.cg.shared.global [%0], [%1], 16;" :: "r"(dst), "l"(src))
#define CP_COMMIT() asm volatile("cp.async.commit_group;" ::: "memory")
#define CP_WAIT0()  asm volatile("cp.async.wait_group 0;" ::: "memory")

// ---------------- smem layout (bytes) ----------------
// SA: [128 t][136] bf16 (A chunk / probs), pitch 272B
// SB: [128 j][264] bf16 (full U), pitch 528B; f32 epilogue buffer overlays SB
#define SA_H 0u
#define SA_L 34816u
#define SB_H 69632u
#define SB_L 137216u
#define OFF_SSU 204800u
#define OFF_SSH 205312u
#define OFF_RM  205824u
#define OFF_RS  206848u
#define SMEM_TOTAL 207872u

// ---------------- U split + su ----------------
__global__ void usplit_kernel(const float* __restrict__ U, const float* __restrict__ w_u) {
    __shared__ float sSu[64];
    int b = blockIdx.x >> 1, jh = blockIdx.x & 1;
    int tid = threadIdx.x, lane = tid & 31;
    float wu = w_u[tid];
    if (tid < 64) sSu[tid] = 0.f;
    __syncthreads();
    const float* Ub = U + (size_t)b * JJ * DD;
    __nv_bfloat16* uh = g_Uhi + (size_t)b * JJ * DD;
    __nv_bfloat16* ul = g_Ulo + (size_t)b * JJ * DD;
    for (int r = 0; r < 64; r++) {
        int j = jh * 64 + r;
        float v = Ub[j * DD + tid];
        uint16_t hi, lo; bsplit(v, hi, lo);
        uh[j * DD + tid] = __ushort_as_bfloat16(hi);
        ul[j * DD + tid] = __ushort_as_bfloat16(lo);
        float p = v * wu;
        #pragma unroll
        for (int o = 16; o; o >>= 1) p += __shfl_xor_sync(0xffffffffu, p, o);
        if (lane == 0) atomicAdd(&sSu[r], p);
    }
    __syncthreads();
    if (tid < 64) g_su[b * JJ + jh * 64 + tid] = sSu[tid];
}

// ---------------- prep: A = H*w_hu hi/lo, sh = H.w_h, G quarter0 = H ----------------
// grid 1024 x 256 thr; block handles 64 rows; thread: row tid>>2, quarter tid&3
__global__ void prep_kernel(const float* __restrict__ H, const float* __restrict__ w_h,
                            const float* __restrict__ w_hu, float* __restrict__ G) {
    __shared__ float sWhu[DD], sWh[DD];
    int tid = threadIdx.x;
    sWhu[tid] = w_hu[tid];
    sWh[tid]  = w_h[tid];
    __syncthreads();
    int r = tid >> 2, q = tid & 3;
    size_t bt = (size_t)blockIdx.x * 64 + r;
    const float4* Hr = (const float4*)(H + bt * DD);
    float* Gr = G + bt * (4 * DD);
    __nv_bfloat16* Ah = g_Ahi + bt * DD;
    __nv_bfloat16* Al = g_Alo + bt * DD;
    float sh = 0.f;
    #pragma unroll
    for (int k = 0; k < 16; k++) {
        int d = q * 64 + k * 4;
        float4 v = Hr[d >> 2];
        float a0 = v.x * sWhu[d],     a1 = v.y * sWhu[d + 1];
        float a2 = v.z * sWhu[d + 2], a3 = v.w * sWhu[d + 3];
        uint16_t h0,l0,h1,l1,h2,l2,h3,l3;
        bsplit(a0,h0,l0); bsplit(a1,h1,l1); bsplit(a2,h2,l2); bsplit(a3,h3,l3);
        *(uint2*)(Ah + d) = make_uint2((uint32_t)h0 | ((uint32_t)h1 << 16),
                                       (uint32_t)h2 | ((uint32_t)h3 << 16));
        *(uint2*)(Al + d) = make_uint2((uint32_t)l0 | ((uint32_t)l1 << 16),
                                       (uint32_t)l2 | ((uint32_t)l3 << 16));
        *(float4*)(Gr + d) = v;
        sh += v.x * sWh[d] + v.y * sWh[d + 1] + v.z * sWh[d + 2] + v.w * sWh[d + 3];
    }
    sh += __shfl_xor_sync(0xffffffffu, sh, 1);
    sh += __shfl_xor_sync(0xffffffffu, sh, 2);
    if (q == 0) g_sh[bt] = sh;
}

// ---------------- main fused kernel ----------------
__global__ void __launch_bounds__(256, 1)
bidaf_main(const float* __restrict__ H, float* __restrict__ G) {
    extern __shared__ char smem[];
    const uint32_t sbase = (uint32_t)__cvta_generic_to_shared(smem);
    const int b = blockIdx.y;
    const int t0 = blockIdx.x * TM;
    const int tid = threadIdx.x;
    const int wid = tid >> 5, lane = tid & 31;
    const int g = lane >> 2, qt = lane & 3;
    const int l16 = lane & 15, lh = lane >> 4;

    float* ssu = (float*)(smem + OFF_SSU);
    float* ssh = (float*)(smem + OFF_SSH);
    float* sRM = (float*)(smem + OFF_RM);
    float* sRS = (float*)(smem + OFF_RS);

    // ---- stage U hi/lo [128 j][256 d] (pitch 528B) + A chunk0 [128 t][0:128 d] ----
    {
        const char* srcH = (const char*)(g_Uhi + (size_t)b * JJ * DD);
        const char* srcL = (const char*)(g_Ulo + (size_t)b * JJ * DD);
        #pragma unroll
        for (int k = 0; k < 16; k++) {
            int idx = tid + 256 * k;
            int j = idx >> 5, c = idx & 31;
            uint32_t dst = sbase + (uint32_t)(j * 528 + c * 16);
            CP_ASYNC16(dst + SB_H, srcH + j * 512 + c * 16);
            CP_ASYNC16(dst + SB_L, srcL + j * 512 + c * 16);
        }
        const char* aH = (const char*)(g_Ahi + (size_t)(b * TT + t0) * DD);
        const char* aL = (const char*)(g_Alo + (size_t)(b * TT + t0) * DD);
        #pragma unroll
        for (int k = 0; k < 8; k++) {
            int idx = tid + 256 * k;
            int t = idx >> 4, c = idx & 15;
            uint32_t dst = sbase + (uint32_t)(t * 272 + c * 16);
            CP_ASYNC16(dst + SA_H, aH + t * 512 + c * 16);
            CP_ASYNC16(dst + SA_L, aL + t * 512 + c * 16);
        }
        CP_COMMIT();
    }
    if (tid < 128) ssu[tid] = g_su[b * JJ + tid];
    else ssh[tid - 128] = g_sh[b * TT + t0 + tid - 128];

    const int wm1 = wid >> 1, wn1 = wid & 1;   // 4x2 warp grid, 32x64 tiles
    float C1[2][8][4];
    #pragma unroll
    for (int mf = 0; mf < 2; mf++)
        #pragma unroll
        for (int nf = 0; nf < 8; nf++)
            #pragma unroll
            for (int q = 0; q < 4; q++) C1[mf][nf][q] = 0.f;

    CP_WAIT0();
    __syncthreads();

    // ================= GEMM1: S[128t][128j], K=256 in 2 chunks =================
    #pragma unroll
    for (int ch = 0; ch < 2; ch++) {
        #pragma unroll
        for (int ks = 0; ks < 8; ks++) {
            uint32_t aH[2][4], aL[2][4];
            #pragma unroll
            for (int mf = 0; mf < 2; mf++) {
                uint32_t ar = sbase + (uint32_t)((wm1 * 32 + mf * 16 + l16) * 272 + ks * 32 + lh * 16);
                ldsm4(aH[mf], ar + SA_H);
                ldsm4(aL[mf], ar + SA_L);
            }
            #pragma unroll
            for (int p = 0; p < 4; p++) {
                uint32_t br = sbase + (uint32_t)((wn1 * 64 + p * 16 + l16) * 528
                                                 + ch * 256 + ks * 32 + lh * 16);
                uint32_t bh[4], bl[4];
                ldsm4(bh, br + SB_H);
                ldsm4(bl, br + SB_L);
                uint32_t B0h[2] = {bh[0], bh[2]}, B1h[2] = {bh[1], bh[3]};
                uint32_t B0l[2] = {bl[0], bl[2]}, B1l[2] = {bl[1], bl[3]};
                #pragma unroll
                for (int mf = 0; mf < 2; mf++) {
                    mma16816(C1[mf][2*p],   aH[mf], B0h);
                    mma16816(C1[mf][2*p],   aL[mf], B0h);
                    mma16816(C1[mf][2*p],   aH[mf], B0l);
                    mma16816(C1[mf][2*p+1], aH[mf], B1h);
                    mma16816(C1[mf][2*p+1], aL[mf], B1h);
                    mma16816(C1[mf][2*p+1], aH[mf], B1l);
                }
            }
        }
        if (ch == 0) {
            __syncthreads();   // done reading A chunk0
            const char* aH = (const char*)(g_Ahi + (size_t)(b * TT + t0) * DD) + 256;
            const char* aL = (const char*)(g_Alo + (size_t)(b * TT + t0) * DD) + 256;
            #pragma unroll
            for (int k = 0; k < 8; k++) {
                int idx = tid + 256 * k;
                int t = idx >> 4, c = idx & 15;
                uint32_t dst = sbase + (uint32_t)(t * 272 + c * 16);
                CP_ASYNC16(dst + SA_H, aH + t * 512 + c * 16);
                CP_ASYNC16(dst + SA_L, aL + t * 512 + c * 16);
            }
            CP_COMMIT();
            CP_WAIT0();
            __syncthreads();
        }
    }

    // ================= softmax over j =================
    #pragma unroll
    for (int mf = 0; mf < 2; mf++) {
        int r0 = wm1 * 32 + mf * 16 + g;
        float m0 = -1e30f, m1 = -1e30f;
        #pragma unroll
        for (int nf = 0; nf < 8; nf++) {
            float2 su2 = *(const float2*)&ssu[wn1 * 64 + nf * 8 + qt * 2];
            C1[mf][nf][0] += su2.x; C1[mf][nf][1] += su2.y;
            C1[mf][nf][2] += su2.x; C1[mf][nf][3] += su2.y;
            m0 = fmaxf(m0, fmaxf(C1[mf][nf][0], C1[mf][nf][1]));
            m1 = fmaxf(m1, fmaxf(C1[mf][nf][2], C1[mf][nf][3]));
        }
        #pragma unroll
        for (int o = 1; o < 4; o <<= 1) {
            m0 = fmaxf(m0, __shfl_xor_sync(0xffffffffu, m0, o));
            m1 = fmaxf(m1, __shfl_xor_sync(0xffffffffu, m1, o));
        }
        if (qt == 0) { sRM[r0 * 2 + wn1] = m0; sRM[(r0 + 8) * 2 + wn1] = m1; }
    }
    __syncthreads();
    #pragma unroll
    for (int mf = 0; mf < 2; mf++) {
        int r0 = wm1 * 32 + mf * 16 + g;
        float M0 = fmaxf(sRM[r0 * 2], sRM[r0 * 2 + 1]);
        float M1 = fmaxf(sRM[(r0 + 8) * 2], sRM[(r0 + 8) * 2 + 1]);
        float s0 = 0.f, s1 = 0.f;
        #pragma unroll
        for (int nf = 0; nf < 8; nf++) {
            C1[mf][nf][0] = __expf(C1[mf][nf][0] - M0);
            C1[mf][nf][1] = __expf(C1[mf][nf][1] - M0);
            C1[mf][nf][2] = __expf(C1[mf][nf][2] - M1);
            C1[mf][nf][3] = __expf(C1[mf][nf][3] - M1);
            s0 += C1[mf][nf][0] + C1[mf][nf][1];
            s1 += C1[mf][nf][2] + C1[mf][nf][3];
        }
        #pragma unroll
        for (int o = 1; o < 4; o <<= 1) {
            s0 += __shfl_xor_sync(0xffffffffu, s0, o);
            s1 += __shfl_xor_sync(0xffffffffu, s1, o);
        }
        if (qt == 0) {
            sRS[r0 * 2 + wn1] = s0; sRS[(r0 + 8) * 2 + wn1] = s1;
            if (wn1 == 0) {
                g_rowmax[b * TT + t0 + r0]     = M0 + ssh[r0];
                g_rowmax[b * TT + t0 + r0 + 8] = M1 + ssh[r0 + 8];
            }
        }
    }
    __syncthreads();
    // normalize + pack probs bf16 hi/lo into SA ([t][j], pitch 272B)
    #pragma unroll
    for (int mf = 0; mf < 2; mf++) {
        int r0 = wm1 * 32 + mf * 16 + g;
        float inv0 = 1.f / (sRS[r0 * 2] + sRS[r0 * 2 + 1]);
        float inv1 = 1.f / (sRS[(r0 + 8) * 2] + sRS[(r0 + 8) * 2 + 1]);
        #pragma unroll
        for (int nf = 0; nf < 8; nf++) {
            int col = wn1 * 64 + nf * 8 + qt * 2;
            float p00 = C1[mf][nf][0] * inv0, p01 = C1[mf][nf][1] * inv0;
            float p10 = C1[mf][nf][2] * inv1, p11 = C1[mf][nf][3] * inv1;
            uint16_t h0,l0,h1,l1,h2,l2,h3,l3;
            bsplit(p00,h0,l0); bsplit(p01,h1,l1); bsplit(p10,h2,l2); bsplit(p11,h3,l3);
            uint32_t o0 = (uint32_t)r0 * 272u + (uint32_t)col * 2u;
            uint32_t o1 = (uint32_t)(r0 + 8) * 272u + (uint32_t)col * 2u;
            *(uint32_t*)(smem + SA_H + o0) = (uint32_t)h0 | ((uint32_t)h1 << 16);
            *(uint32_t*)(smem + SA_L + o0) = (uint32_t)l0 | ((uint32_t)l1 << 16);
            *(uint32_t*)(smem + SA_H + o1) = (uint32_t)h2 | ((uint32_t)h3 << 16);
            *(uint32_t*)(smem + SA_L + o1) = (uint32_t)l2 | ((uint32_t)l3 << 16);
        }
    }
    __syncthreads();

    // ================= GEMM2: C2Q[128t][256d] = P @ U (trans-B on U) =================
    const int wm2 = wid >> 2, wn2 = wid & 3;   // 2x4 warp grid, 64x64 tiles
    float C2[4][8][4];
    #pragma unroll
    for (int mf = 0; mf < 4; mf++)
        #pragma unroll
        for (int nf = 0; nf < 8; nf++)
            #pragma unroll
            for (int q = 0; q < 4; q++) C2[mf][nf][q] = 0.f;

    #pragma unroll
    for (int ks = 0; ks < 8; ks++) {
        uint32_t aH[4][4], aL[4][4];
        #pragma unroll
        for (int mf = 0; mf < 4; mf++) {
            uint32_t ar = sbase + (uint32_t)((wm2 * 64 + mf * 16 + l16) * 272 + ks * 32 + lh * 16);
            ldsm4(aH[mf], ar + SA_H);
            ldsm4(aL[mf], ar + SA_L);
        }
        #pragma unroll
        for (int p = 0; p < 4; p++) {
            uint32_t br = sbase + (uint32_t)((ks * 16 + l16) * 528
                                             + (wn2 * 64 + p * 16 + lh * 8) * 2);
            uint32_t bh[4], bl[4];
            ldsm4t(bh, br + SB_H);
            ldsm4t(bl, br + SB_L);
            uint32_t B0h[2] = {bh[0], bh[1]}, B1h[2] = {bh[2], bh[3]};
            uint32_t B0l[2] = {bl[0], bl[1]}, B1l[2] = {bl[2], bl[3]};
            #pragma unroll
            for (int mf = 0; mf < 4; mf++) {
                mma16816(C2[mf][2*p],   aH[mf], B0h);
                mma16816(C2[mf][2*p],   aL[mf], B0h);
                mma16816(C2[mf][2*p],   aH[mf], B0l);
                mma16816(C2[mf][2*p+1], aH[mf], B1h);
                mma16816(C2[mf][2*p+1], aL[mf], B1h);
                mma16816(C2[mf][2*p+1], aH[mf], B1l);
            }
        }
    }
    __syncthreads();   // U dead -> SB becomes f32 epilogue buffer

    // ================= epilogue: G quarters 1,2 =================
    {
        float* sEpi = (float*)(smem + SB_H);   // [128][264] f32
        #pragma unroll
        for (int mf = 0; mf < 4; mf++) {
            int r0 = wm2 * 64 + mf * 16 + g;
            #pragma unroll
            for (int nf = 0; nf < 8; nf++) {
                int c0 = wn2 * 64 + nf * 8 + qt * 2;
                *(float2*)&sEpi[r0 * 264 + c0]       = make_float2(C2[mf][nf][0], C2[mf][nf][1]);
                *(float2*)&sEpi[(r0 + 8) * 264 + c0] = make_float2(C2[mf][nf][2], C2[mf][nf][3]);
            }
        }
        __syncthreads();
        #pragma unroll 2
        for (int r = 0; r < 16; r++) {
            int row = wid * 16 + r;
            size_t rowg = (size_t)(b * TT + t0 + row);
            const float* Hrow = H + rowg * DD;
            float* Grow = G + rowg * (4 * DD);
            #pragma unroll
            for (int i = 0; i < 4; i++) {
                int d = 2 * lane + 64 * i;
                float2 cq = *(float2*)&sEpi[row * 264 + d];
                float2 h = *(const float2*)&Hrow[d];
                *(float2*)&Grow[DD + d] = cq;
                *(float2*)&Grow[2 * DD + d] = make_float2(h.x * cq.x, h.y * cq.y);
            }
        }
    }
}

// ---------------- b_att = softmax_t(rowmax); also zero q2c accumulators ----------------
__global__ void batt_kernel() {
    __shared__ float red[8];
    int b = blockIdx.x;
    int tid = threadIdx.x;
    int w = tid >> 5, lane = tid & 31;
    float v[4];
    float m = -1e30f;
    #pragma unroll
    for (int k = 0; k < 4; k++) { v[k] = g_rowmax[b * TT + tid + 256 * k]; m = fmaxf(m, v[k]); }
    #pragma unroll
    for (int o = 16; o; o >>= 1) m = fmaxf(m, __shfl_xor_sync(0xffffffffu, m, o));
    if (lane == 0) red[w] = m;
    __syncthreads();
    float M = red[0];
    #pragma unroll
    for (int i = 1; i < 8; i++) M = fmaxf(M, red[i]);
    __syncthreads();
    float e[4], sum = 0.f;
    #pragma unroll
    for (int k = 0; k < 4; k++) { e[k] = __expf(v[k] - M); sum += e[k]; }
    #pragma unroll
    for (int o = 16; o; o >>= 1) sum += __shfl_xor_sync(0xffffffffu, sum, o);
    if (lane == 0) red[w] = sum;
    __syncthreads();
    float S = 0.f;
    #pragma unroll
    for (int i = 0; i < 8; i++) S += red[i];
    float inv = 1.f / S;
    #pragma unroll
    for (int k = 0; k < 4; k++) g_batt[b * TT + tid + 256 * k] = e[k] * inv;
}

// ---------------- Q2C partials: grid 512 = (b, tchunk) ----------------
__global__ void q2cp_kernel(const float* __restrict__ H) {
    int b = blockIdx.x >> 3, ck = blockIdx.x & 7;
    int tid = threadIdx.x;                  // d
    int t0 = ck * 128;
    const float* Hb = H + ((size_t)(b * TT + t0)) * DD + tid;
    const float* bat = g_batt + b * TT + t0;
    float q = 0.f;
    #pragma unroll 8
    for (int t = 0; t < 128; t++) q += bat[t] * Hb[(size_t)t * DD];
    g_q2cp[(size_t)(b * 8 + ck) * DD + tid] = q;
}

__global__ void q2cr_kernel() {
    int b = blockIdx.x, tid = threadIdx.x;
    float s = 0.f;
    #pragma unroll
    for (int c = 0; c < 8; c++) s += g_q2cp[(size_t)(b * 8 + c) * DD + tid];
    g_q2c[b * DD + tid] = s;
}

// ---------------- G quarter 3 = H * Q2C ----------------
__global__ void g3_kernel(const float* __restrict__ H, float* __restrict__ G) {
    size_t base = (size_t)blockIdx.x * 1024 + threadIdx.x;
    #pragma unroll
    for (int k = 0; k < 4; k++) {
        size_t idx = base + 256 * k;           // float4 units
        int d4 = (int)(idx & 63);
        size_t bt = idx >> 6;
        int b = (int)(bt >> 10);
        float4 h = ((const float4*)H)[idx];
        float4 q = ((const float4*)g_q2c)[b * 64 + d4];
        float4 o = make_float4(h.x * q.x, h.y * q.y, h.z * q.z, h.w * q.w);
        ((float4*)G)[bt * 256 + 192 + d4] = o;
    }
}

extern "C" void kernel_launch(void* const* d_in, const int* in_sizes, int n_in,
                              void* d_out, int out_size) {
    const float* H    = (const float*)d_in[0];
    const float* U    = (const float*)d_in[1];
    const float* w_h  = (const float*)d_in[2];
    const float* w_u  = (const float*)d_in[3];
    const float* w_hu = (const float*)d_in[4];
    float* G = (float*)d_out;

    cudaFuncSetAttribute(bidaf_main, cudaFuncAttributeMaxDynamicSharedMemorySize, SMEM_TOTAL);

    usplit_kernel<<<BB * 2, 256>>>(U, w_u);
    prep_kernel<<<BB * TT / 64, 256>>>(H, w_h, w_hu, G);
    bidaf_main<<<dim3(TT / TM, BB), 256, SMEM_TOTAL>>>(H, G);
    batt_kernel<<<BB, 256>>>();
    q2cp_kernel<<<BB * 8, 256>>>(H);
    q2cr_kernel<<<BB, 256>>>();
    g3_kernel<<<(BB * TT * DD / 4) / 1024, 256>>>(H, G);
}

// round 10
// speedup vs baseline: 1.5841x; 1.5614x over previous
#include <cuda_runtime.h>
#include <cuda_fp16.h>
#include <cstdint>
#include <math.h>

#define BB 64
#define TT 1024
#define JJ 128
#define DD 256
#define TM 128   // t rows per CTA tile

// ---------------- device scratch ----------------
__device__ __align__(16) __half g_Uh[BB * JJ * DD];
__device__ float g_su[BB * JJ];
__device__ float g_rowmax[BB * TT];
__device__ float g_batt[BB * TT];
__device__ float g_q2cp[8 * BB * DD];
__device__ float g_q2c[BB * DD];

// mma.sync m16n8k16 fp16 -> f32
__device__ __forceinline__ void mma16816(float* c, const uint32_t* a, const uint32_t* b) {
    asm volatile(
        "mma.sync.aligned.m16n8k16.row.col.f32.f16.f16.f32 "
        "{%0,%1,%2,%3}, {%4,%5,%6,%7}, {%8,%9}, {%0,%1,%2,%3};"
        : "+f"(c[0]), "+f"(c[1]), "+f"(c[2]), "+f"(c[3])
        : "r"(a[0]), "r"(a[1]), "r"(a[2]), "r"(a[3]), "r"(b[0]), "r"(b[1]));
}
__device__ __forceinline__ void ldsm4(uint32_t* r, uint32_t addr) {
    asm volatile("ldmatrix.sync.aligned.m8n8.x4.shared.b16 {%0,%1,%2,%3}, [%4];"
        : "=r"(r[0]), "=r"(r[1]), "=r"(r[2]), "=r"(r[3]) : "r"(addr));
}
__device__ __forceinline__ void ldsm4t(uint32_t* r, uint32_t addr) {
    asm volatile("ldmatrix.sync.aligned.m8n8.x4.trans.shared.b16 {%0,%1,%2,%3}, [%4];"
        : "=r"(r[0]), "=r"(r[1]), "=r"(r[2]), "=r"(r[3]) : "r"(addr));
}
#define CP_ASYNC16(dst, src) \
    asm volatile("cp.async.cg.shared.global [%0], [%1], 16;" :: "r"(dst), "l"(src))
#define CP_COMMIT() asm volatile("cp.async.commit_group;" ::: "memory")
#define CP_WAIT0()  asm volatile("cp.async.wait_group 0;" ::: "memory")

// ---------------- smem layout (bytes) ----------------
// SA: [128 t][264] fp16 (A full-K; later probs at pitch 272B), pitch 528B
// SB: [128 j][264] fp16 (U full), pitch 528B
// epilogue f32 [128][264] overlays SA+SB (both dead by then)
#define SA 0u
#define SB 67584u
#define OFF_SSU 135168u
#define OFF_SSH 135680u
#define OFF_RM  136192u
#define OFF_RS  137216u
#define OFF_WHU 138240u
#define OFF_WH  139264u
#define SMEM_TOTAL 140288u

// ---------------- U fp16 convert + su ----------------
__global__ void usplit_kernel(const float* __restrict__ U, const float* __restrict__ w_u) {
    __shared__ float sSu[64];
    int b = blockIdx.x >> 1, jh = blockIdx.x & 1;
    int tid = threadIdx.x, lane = tid & 31;
    float wu = w_u[tid];
    if (tid < 64) sSu[tid] = 0.f;
    __syncthreads();
    const float* Ub = U + (size_t)b * JJ * DD;
    __half* uh = g_Uh + (size_t)b * JJ * DD;
    for (int r = 0; r < 64; r++) {
        int j = jh * 64 + r;
        float v = Ub[j * DD + tid];
        uh[j * DD + tid] = __float2half_rn(v);
        float p = v * wu;
        #pragma unroll
        for (int o = 16; o; o >>= 1) p += __shfl_xor_sync(0xffffffffu, p, o);
        if (lane == 0) atomicAdd(&sSu[r], p);
    }
    __syncthreads();
    if (tid < 64) g_su[b * JJ + jh * 64 + tid] = sSu[tid];
}

// ---------------- main fused kernel ----------------
__global__ void __launch_bounds__(256, 1)
bidaf_main(const float* __restrict__ H, const float* __restrict__ w_h,
           const float* __restrict__ w_hu, float* __restrict__ G) {
    extern __shared__ char smem[];
    const uint32_t sbase = (uint32_t)__cvta_generic_to_shared(smem);
    const int b = blockIdx.y;
    const int t0 = blockIdx.x * TM;
    const int tid = threadIdx.x;
    const int wid = tid >> 5, lane = tid & 31;
    const int g = lane >> 2, qt = lane & 3;
    const int l16 = lane & 15, lh = lane >> 4;

    float* ssu  = (float*)(smem + OFF_SSU);
    float* ssh  = (float*)(smem + OFF_SSH);
    float* sRM  = (float*)(smem + OFF_RM);
    float* sRS  = (float*)(smem + OFF_RS);
    float* sWhu = (float*)(smem + OFF_WHU);
    float* sWh  = (float*)(smem + OFF_WH);

    // ---- cp.async U [128 j][256 d] fp16 into SB (pitch 528B) ----
    {
        const char* src = (const char*)(g_Uh + (size_t)b * JJ * DD);
        #pragma unroll
        for (int k = 0; k < 16; k++) {
            int idx = tid + 256 * k;          // 4096 granules of 16B
            int j = idx >> 5, c = idx & 31;
            CP_ASYNC16(sbase + SB + (uint32_t)(j * 528 + c * 16), src + j * 512 + c * 16);
        }
        CP_COMMIT();
    }

    sWhu[tid] = w_hu[tid];
    sWh[tid]  = w_h[tid];
    if (tid < JJ) ssu[tid] = g_su[b * JJ + tid];
    __syncthreads();

    // ---- stage A = fp16(H*w_hu) full-K [128][256] + sh accumulation ----
    float shreg[16];
    {
        const float4* H4 = (const float4*)(H + ((size_t)(b * TT + t0)) * DD);
        #pragma unroll
        for (int rk = 0; rk < 16; rk++) {
            int row = wid + 8 * rk;
            float sh = 0.f;
            #pragma unroll
            for (int h = 0; h < 2; h++) {
                int d = h * 128 + lane * 4;
                float4 v = H4[row * 64 + (d >> 2)];
                __half2 p01 = __floats2half2_rn(v.x * sWhu[d],     v.y * sWhu[d + 1]);
                __half2 p23 = __floats2half2_rn(v.z * sWhu[d + 2], v.w * sWhu[d + 3]);
                *(uint2*)(smem + SA + row * 528 + d * 2) =
                    make_uint2(*(uint32_t*)&p01, *(uint32_t*)&p23);
                sh += v.x * sWh[d] + v.y * sWh[d + 1] + v.z * sWh[d + 2] + v.w * sWh[d + 3];
            }
            #pragma unroll
            for (int o = 16; o; o >>= 1) sh += __shfl_xor_sync(0xffffffffu, sh, o);
            shreg[rk] = sh;
        }
    }
    if (lane == 0) {
        #pragma unroll
        for (int k = 0; k < 16; k++) ssh[wid + 8 * k] = shreg[k];
    }

    const int wm1 = wid >> 1, wn1 = wid & 1;   // 4x2 warp grid, 32x64 tiles
    float C1[2][8][4];
    #pragma unroll
    for (int mf = 0; mf < 2; mf++)
        #pragma unroll
        for (int nf = 0; nf < 8; nf++)
            #pragma unroll
            for (int q = 0; q < 4; q++) C1[mf][nf][q] = 0.f;

    CP_WAIT0();
    __syncthreads();

    // ================= GEMM1: S[128t][128j], K=256, single pass =================
    #pragma unroll
    for (int ks = 0; ks < 16; ks++) {
        uint32_t a[2][4];
        #pragma unroll
        for (int mf = 0; mf < 2; mf++) {
            uint32_t ar = sbase + SA + (uint32_t)((wm1 * 32 + mf * 16 + l16) * 528 + ks * 32 + lh * 16);
            ldsm4(a[mf], ar);
        }
        #pragma unroll
        for (int p = 0; p < 4; p++) {
            uint32_t br = sbase + SB + (uint32_t)((wn1 * 64 + p * 16 + l16) * 528 + ks * 32 + lh * 16);
            uint32_t bb[4];
            ldsm4(bb, br);
            uint32_t B0[2] = {bb[0], bb[2]}, B1[2] = {bb[1], bb[3]};
            #pragma unroll
            for (int mf = 0; mf < 2; mf++) {
                mma16816(C1[mf][2*p],   a[mf], B0);
                mma16816(C1[mf][2*p+1], a[mf], B1);
            }
        }
    }
    __syncthreads();   // A dead; SA reused for probs below

    // ================= softmax over j =================
    #pragma unroll
    for (int mf = 0; mf < 2; mf++) {
        int r0 = wm1 * 32 + mf * 16 + g;
        float m0 = -1e30f, m1 = -1e30f;
        #pragma unroll
        for (int nf = 0; nf < 8; nf++) {
            float2 su2 = *(const float2*)&ssu[wn1 * 64 + nf * 8 + qt * 2];
            C1[mf][nf][0] += su2.x; C1[mf][nf][1] += su2.y;
            C1[mf][nf][2] += su2.x; C1[mf][nf][3] += su2.y;
            m0 = fmaxf(m0, fmaxf(C1[mf][nf][0], C1[mf][nf][1]));
            m1 = fmaxf(m1, fmaxf(C1[mf][nf][2], C1[mf][nf][3]));
        }
        #pragma unroll
        for (int o = 1; o < 4; o <<= 1) {
            m0 = fmaxf(m0, __shfl_xor_sync(0xffffffffu, m0, o));
            m1 = fmaxf(m1, __shfl_xor_sync(0xffffffffu, m1, o));
        }
        if (qt == 0) { sRM[r0 * 2 + wn1] = m0; sRM[(r0 + 8) * 2 + wn1] = m1; }
    }
    __syncthreads();
    #pragma unroll
    for (int mf = 0; mf < 2; mf++) {
        int r0 = wm1 * 32 + mf * 16 + g;
        float M0 = fmaxf(sRM[r0 * 2], sRM[r0 * 2 + 1]);
        float M1 = fmaxf(sRM[(r0 + 8) * 2], sRM[(r0 + 8) * 2 + 1]);
        float s0 = 0.f, s1 = 0.f;
        #pragma unroll
        for (int nf = 0; nf < 8; nf++) {
            C1[mf][nf][0] = __expf(C1[mf][nf][0] - M0);
            C1[mf][nf][1] = __expf(C1[mf][nf][1] - M0);
            C1[mf][nf][2] = __expf(C1[mf][nf][2] - M1);
            C1[mf][nf][3] = __expf(C1[mf][nf][3] - M1);
            s0 += C1[mf][nf][0] + C1[mf][nf][1];
            s1 += C1[mf][nf][2] + C1[mf][nf][3];
        }
        #pragma unroll
        for (int o = 1; o < 4; o <<= 1) {
            s0 += __shfl_xor_sync(0xffffffffu, s0, o);
            s1 += __shfl_xor_sync(0xffffffffu, s1, o);
        }
        if (qt == 0) {
            sRS[r0 * 2 + wn1] = s0; sRS[(r0 + 8) * 2 + wn1] = s1;
            if (wn1 == 0) {
                g_rowmax[b * TT + t0 + r0]     = M0 + ssh[r0];
                g_rowmax[b * TT + t0 + r0 + 8] = M1 + ssh[r0 + 8];
            }
        }
    }
    __syncthreads();
    // normalize + pack probs fp16 into SA (pitch 272B)
    #pragma unroll
    for (int mf = 0; mf < 2; mf++) {
        int r0 = wm1 * 32 + mf * 16 + g;
        float inv0 = 1.f / (sRS[r0 * 2] + sRS[r0 * 2 + 1]);
        float inv1 = 1.f / (sRS[(r0 + 8) * 2] + sRS[(r0 + 8) * 2 + 1]);
        #pragma unroll
        for (int nf = 0; nf < 8; nf++) {
            int col = wn1 * 64 + nf * 8 + qt * 2;
            __half2 p0 = __floats2half2_rn(C1[mf][nf][0] * inv0, C1[mf][nf][1] * inv0);
            __half2 p1 = __floats2half2_rn(C1[mf][nf][2] * inv1, C1[mf][nf][3] * inv1);
            *(uint32_t*)(smem + SA + r0 * 272 + col * 2)       = *(uint32_t*)&p0;
            *(uint32_t*)(smem + SA + (r0 + 8) * 272 + col * 2) = *(uint32_t*)&p1;
        }
    }
    __syncthreads();

    // ================= GEMM2: C2Q[128t][256d] = P @ U (trans-B on U) =================
    const int wm2 = wid >> 2, wn2 = wid & 3;   // 2x4 warp grid, 64x64 tiles
    float C2[4][8][4];
    #pragma unroll
    for (int mf = 0; mf < 4; mf++)
        #pragma unroll
        for (int nf = 0; nf < 8; nf++)
            #pragma unroll
            for (int q = 0; q < 4; q++) C2[mf][nf][q] = 0.f;

    #pragma unroll
    for (int ks = 0; ks < 8; ks++) {
        uint32_t a[4][4];
        #pragma unroll
        for (int mf = 0; mf < 4; mf++) {
            uint32_t ar = sbase + SA + (uint32_t)((wm2 * 64 + mf * 16 + l16) * 272 + ks * 32 + lh * 16);
            ldsm4(a[mf], ar);
        }
        #pragma unroll
        for (int p = 0; p < 4; p++) {
            uint32_t br = sbase + SB + (uint32_t)((ks * 16 + l16) * 528
                                                  + (wn2 * 64 + p * 16 + lh * 8) * 2);
            uint32_t bb[4];
            ldsm4t(bb, br);
            uint32_t B0[2] = {bb[0], bb[1]}, B1[2] = {bb[2], bb[3]};
            #pragma unroll
            for (int mf = 0; mf < 4; mf++) {
                mma16816(C2[mf][2*p],   a[mf], B0);
                mma16816(C2[mf][2*p+1], a[mf], B1);
            }
        }
    }
    __syncthreads();   // SA+SB dead -> f32 epilogue buffer overlays from 0

    // ================= epilogue: G quarters 0,1,2 =================
    {
        float* sEpi = (float*)smem;            // [128][264] f32
        #pragma unroll
        for (int mf = 0; mf < 4; mf++) {
            int r0 = wm2 * 64 + mf * 16 + g;
            #pragma unroll
            for (int nf = 0; nf < 8; nf++) {
                int c0 = wn2 * 64 + nf * 8 + qt * 2;
                *(float2*)&sEpi[r0 * 264 + c0]       = make_float2(C2[mf][nf][0], C2[mf][nf][1]);
                *(float2*)&sEpi[(r0 + 8) * 264 + c0] = make_float2(C2[mf][nf][2], C2[mf][nf][3]);
            }
        }
        __syncthreads();
        #pragma unroll 2
        for (int r = 0; r < 16; r++) {
            int row = wid * 16 + r;
            size_t rowg = (size_t)(b * TT + t0 + row);
            const float* Hrow = H + rowg * DD;
            float* Grow = G + rowg * (4 * DD);
            #pragma unroll
            for (int i = 0; i < 4; i++) {
                int d = 2 * lane + 64 * i;
                float2 cq = *(float2*)&sEpi[row * 264 + d];
                float2 h = *(const float2*)&Hrow[d];
                *(float2*)&Grow[d] = h;
                *(float2*)&Grow[DD + d] = cq;
                *(float2*)&Grow[2 * DD + d] = make_float2(h.x * cq.x, h.y * cq.y);
            }
        }
    }
}

// ---------------- b_att = softmax_t(rowmax) ----------------
__global__ void batt_kernel() {
    __shared__ float red[8];
    int b = blockIdx.x;
    int tid = threadIdx.x;
    int w = tid >> 5, lane = tid & 31;
    float v[4];
    float m = -1e30f;
    #pragma unroll
    for (int k = 0; k < 4; k++) { v[k] = g_rowmax[b * TT + tid + 256 * k]; m = fmaxf(m, v[k]); }
    #pragma unroll
    for (int o = 16; o; o >>= 1) m = fmaxf(m, __shfl_xor_sync(0xffffffffu, m, o));
    if (lane == 0) red[w] = m;
    __syncthreads();
    float M = red[0];
    #pragma unroll
    for (int i = 1; i < 8; i++) M = fmaxf(M, red[i]);
    __syncthreads();
    float e[4], sum = 0.f;
    #pragma unroll
    for (int k = 0; k < 4; k++) { e[k] = __expf(v[k] - M); sum += e[k]; }
    #pragma unroll
    for (int o = 16; o; o >>= 1) sum += __shfl_xor_sync(0xffffffffu, sum, o);
    if (lane == 0) red[w] = sum;
    __syncthreads();
    float S = 0.f;
    #pragma unroll
    for (int i = 0; i < 8; i++) S += red[i];
    float inv = 1.f / S;
    #pragma unroll
    for (int k = 0; k < 4; k++) g_batt[b * TT + tid + 256 * k] = e[k] * inv;
}

// ---------------- Q2C partials + reduce ----------------
__global__ void q2cp_kernel(const float* __restrict__ H) {
    int b = blockIdx.x >> 3, ck = blockIdx.x & 7;
    int tid = threadIdx.x;
    int t0 = ck * 128;
    const float* Hb = H + ((size_t)(b * TT + t0)) * DD + tid;
    const float* bat = g_batt + b * TT + t0;
    float q = 0.f;
    #pragma unroll 8
    for (int t = 0; t < 128; t++) q += bat[t] * Hb[(size_t)t * DD];
    g_q2cp[(size_t)(b * 8 + ck) * DD + tid] = q;
}

__global__ void q2cr_kernel() {
    int b = blockIdx.x, tid = threadIdx.x;
    float s = 0.f;
    #pragma unroll
    for (int c = 0; c < 8; c++) s += g_q2cp[(size_t)(b * 8 + c) * DD + tid];
    g_q2c[b * DD + tid] = s;
}

// ---------------- G quarter 3 = H * Q2C ----------------
__global__ void g3_kernel(const float* __restrict__ H, float* __restrict__ G) {
    size_t base = (size_t)blockIdx.x * 1024 + threadIdx.x;
    #pragma unroll
    for (int k = 0; k < 4; k++) {
        size_t idx = base + 256 * k;           // float4 units
        int d4 = (int)(idx & 63);
        size_t bt = idx >> 6;
        int b = (int)(bt >> 10);
        float4 h = ((const float4*)H)[idx];
        float4 q = ((const float4*)g_q2c)[b * 64 + d4];
        float4 o = make_float4(h.x * q.x, h.y * q.y, h.z * q.z, h.w * q.w);
        ((float4*)G)[bt * 256 + 192 + d4] = o;
    }
}

extern "C" void kernel_launch(void* const* d_in, const int* in_sizes, int n_in,
                              void* d_out, int out_size) {
    const float* H    = (const float*)d_in[0];
    const float* U    = (const float*)d_in[1];
    const float* w_h  = (const float*)d_in[2];
    const float* w_u  = (const float*)d_in[3];
    const float* w_hu = (const float*)d_in[4];
    float* G = (float*)d_out;

    cudaFuncSetAttribute(bidaf_main, cudaFuncAttributeMaxDynamicSharedMemorySize, SMEM_TOTAL);

    usplit_kernel<<<BB * 2, 256>>>(U, w_u);
    bidaf_main<<<dim3(TT / TM, BB), 256, SMEM_TOTAL>>>(H, w_h, w_hu, G);
    batt_kernel<<<BB, 256>>>();
    q2cp_kernel<<<BB * 8, 256>>>(H);
    q2cr_kernel<<<BB, 256>>>();
    g3_kernel<<<(BB * TT * DD / 4) / 1024, 256>>>(H, G);
}

// round 11
// speedup vs baseline: 2.3048x; 1.4550x over previous
#include <cuda_runtime.h>
#include <cuda_fp16.h>
#include <cstdint>
#include <math.h>

#define BB 64
#define TT 1024
#define JJ 128
#define DD 256
#define TM 128   // t rows per CTA tile

// ---------------- device scratch ----------------
__device__ __align__(16) __half g_Uh[BB * JJ * DD];
__device__ float g_su[BB * JJ];
__device__ float g_rowmax[BB * TT];
__device__ float g_q2cp[8 * BB * DD];   // per-(b,t-chunk) unnormalized partials
__device__ float g_q2c[BB * DD];

// mma.sync m16n8k16 fp16 -> f32
__device__ __forceinline__ void mma16816(float* c, const uint32_t* a, const uint32_t* b) {
    asm volatile(
        "mma.sync.aligned.m16n8k16.row.col.f32.f16.f16.f32 "
        "{%0,%1,%2,%3}, {%4,%5,%6,%7}, {%8,%9}, {%0,%1,%2,%3};"
        : "+f"(c[0]), "+f"(c[1]), "+f"(c[2]), "+f"(c[3])
        : "r"(a[0]), "r"(a[1]), "r"(a[2]), "r"(a[3]), "r"(b[0]), "r"(b[1]));
}
__device__ __forceinline__ void ldsm4(uint32_t* r, uint32_t addr) {
    asm volatile("ldmatrix.sync.aligned.m8n8.x4.shared.b16 {%0,%1,%2,%3}, [%4];"
        : "=r"(r[0]), "=r"(r[1]), "=r"(r[2]), "=r"(r[3]) : "r"(addr));
}
__device__ __forceinline__ void ldsm4t(uint32_t* r, uint32_t addr) {
    asm volatile("ldmatrix.sync.aligned.m8n8.x4.trans.shared.b16 {%0,%1,%2,%3}, [%4];"
        : "=r"(r[0]), "=r"(r[1]), "=r"(r[2]), "=r"(r[3]) : "r"(addr));
}
#define CP_ASYNC16(dst, src) \
    asm volatile("cp.async.cg.shared.global [%0], [%1], 16;" :: "r"(dst), "l"(src))
#define CP_COMMIT() asm volatile("cp.async.commit_group;" ::: "memory")
#define CP_WAIT0()  asm volatile("cp.async.wait_group 0;" ::: "memory")

// ---------------- smem layout (bytes) ----------------
// SA: [128 t][264] fp16 (A full-K; later probs at pitch 272B), pitch 528B
// SB: [128 j][264] fp16 (U full), pitch 528B
// epilogue f32 [128][264] overlays SA+SB
#define SA 0u
#define SB 67584u
#define OFF_SSU 135168u
#define OFF_SSH 135680u
#define OFF_RM  136192u
#define OFF_RS  137216u
#define OFF_WHU 138240u
#define OFF_WH  139264u
#define OFF_SBM 140288u   // [128] rowmax (f32)
#define OFF_SLM 140800u   // scalar localM (padded 16B)
#define OFF_SQ  140816u   // [8][256] f32 partial-q2c reduce
#define SMEM_TOTAL 149008u

// ---------------- U fp16 convert + su ----------------
__global__ void usplit_kernel(const float* __restrict__ U, const float* __restrict__ w_u) {
    __shared__ float sSu[64];
    int b = blockIdx.x >> 1, jh = blockIdx.x & 1;
    int tid = threadIdx.x, lane = tid & 31;
    float wu = w_u[tid];
    if (tid < 64) sSu[tid] = 0.f;
    __syncthreads();
    const float* Ub = U + (size_t)b * JJ * DD;
    __half* uh = g_Uh + (size_t)b * JJ * DD;
    for (int r = 0; r < 64; r++) {
        int j = jh * 64 + r;
        float v = Ub[j * DD + tid];
        uh[j * DD + tid] = __float2half_rn(v);
        float p = v * wu;
        #pragma unroll
        for (int o = 16; o; o >>= 1) p += __shfl_xor_sync(0xffffffffu, p, o);
        if (lane == 0) atomicAdd(&sSu[r], p);
    }
    __syncthreads();
    if (tid < 64) g_su[b * JJ + jh * 64 + tid] = sSu[tid];
}

// ---------------- main fused kernel ----------------
__global__ void __launch_bounds__(256, 1)
bidaf_main(const float* __restrict__ H, const float* __restrict__ w_h,
           const float* __restrict__ w_hu, float* __restrict__ G) {
    extern __shared__ char smem[];
    const uint32_t sbase = (uint32_t)__cvta_generic_to_shared(smem);
    const int b = blockIdx.y;
    const int t0 = blockIdx.x * TM;
    const int tid = threadIdx.x;
    const int wid = tid >> 5, lane = tid & 31;
    const int g = lane >> 2, qt = lane & 3;
    const int l16 = lane & 15, lh = lane >> 4;

    float* ssu  = (float*)(smem + OFF_SSU);
    float* ssh  = (float*)(smem + OFF_SSH);
    float* sRM  = (float*)(smem + OFF_RM);
    float* sRS  = (float*)(smem + OFF_RS);
    float* sWhu = (float*)(smem + OFF_WHU);
    float* sWh  = (float*)(smem + OFF_WH);
    float* sBM  = (float*)(smem + OFF_SBM);
    float* sLM  = (float*)(smem + OFF_SLM);
    float* sQ   = (float*)(smem + OFF_SQ);

    // ---- cp.async U [128 j][256 d] fp16 into SB (pitch 528B) ----
    {
        const char* src = (const char*)(g_Uh + (size_t)b * JJ * DD);
        #pragma unroll
        for (int k = 0; k < 16; k++) {
            int idx = tid + 256 * k;
            int j = idx >> 5, c = idx & 31;
            CP_ASYNC16(sbase + SB + (uint32_t)(j * 528 + c * 16), src + j * 512 + c * 16);
        }
        CP_COMMIT();
    }

    sWhu[tid] = w_hu[tid];
    sWh[tid]  = w_h[tid];
    if (tid < JJ) ssu[tid] = g_su[b * JJ + tid];
    __syncthreads();

    // ---- stage A = fp16(H*w_hu) full-K [128][256] + sh accumulation ----
    float shreg[16];
    {
        const float4* H4 = (const float4*)(H + ((size_t)(b * TT + t0)) * DD);
        #pragma unroll
        for (int rk = 0; rk < 16; rk++) {
            int row = wid + 8 * rk;
            float sh = 0.f;
            #pragma unroll
            for (int h = 0; h < 2; h++) {
                int d = h * 128 + lane * 4;
                float4 v = H4[row * 64 + (d >> 2)];
                __half2 p01 = __floats2half2_rn(v.x * sWhu[d],     v.y * sWhu[d + 1]);
                __half2 p23 = __floats2half2_rn(v.z * sWhu[d + 2], v.w * sWhu[d + 3]);
                *(uint2*)(smem + SA + row * 528 + d * 2) =
                    make_uint2(*(uint32_t*)&p01, *(uint32_t*)&p23);
                sh += v.x * sWh[d] + v.y * sWh[d + 1] + v.z * sWh[d + 2] + v.w * sWh[d + 3];
            }
            #pragma unroll
            for (int o = 16; o; o >>= 1) sh += __shfl_xor_sync(0xffffffffu, sh, o);
            shreg[rk] = sh;
        }
    }
    if (lane == 0) {
        #pragma unroll
        for (int k = 0; k < 16; k++) ssh[wid + 8 * k] = shreg[k];
    }

    const int wm1 = wid >> 1, wn1 = wid & 1;   // 4x2 warp grid, 32x64 tiles
    float C1[2][8][4];
    #pragma unroll
    for (int mf = 0; mf < 2; mf++)
        #pragma unroll
        for (int nf = 0; nf < 8; nf++)
            #pragma unroll
            for (int q = 0; q < 4; q++) C1[mf][nf][q] = 0.f;

    CP_WAIT0();
    __syncthreads();

    // ================= GEMM1: S[128t][128j], K=256, single pass =================
    #pragma unroll
    for (int ks = 0; ks < 16; ks++) {
        uint32_t a[2][4];
        #pragma unroll
        for (int mf = 0; mf < 2; mf++) {
            uint32_t ar = sbase + SA + (uint32_t)((wm1 * 32 + mf * 16 + l16) * 528 + ks * 32 + lh * 16);
            ldsm4(a[mf], ar);
        }
        #pragma unroll
        for (int p = 0; p < 4; p++) {
            uint32_t br = sbase + SB + (uint32_t)((wn1 * 64 + p * 16 + l16) * 528 + ks * 32 + lh * 16);
            uint32_t bb[4];
            ldsm4(bb, br);
            uint32_t B0[2] = {bb[0], bb[2]}, B1[2] = {bb[1], bb[3]};
            #pragma unroll
            for (int mf = 0; mf < 2; mf++) {
                mma16816(C1[mf][2*p],   a[mf], B0);
                mma16816(C1[mf][2*p+1], a[mf], B1);
            }
        }
    }
    __syncthreads();   // A dead; SA reused for probs below

    // ================= softmax over j =================
    #pragma unroll
    for (int mf = 0; mf < 2; mf++) {
        int r0 = wm1 * 32 + mf * 16 + g;
        float m0 = -1e30f, m1 = -1e30f;
        #pragma unroll
        for (int nf = 0; nf < 8; nf++) {
            float2 su2 = *(const float2*)&ssu[wn1 * 64 + nf * 8 + qt * 2];
            C1[mf][nf][0] += su2.x; C1[mf][nf][1] += su2.y;
            C1[mf][nf][2] += su2.x; C1[mf][nf][3] += su2.y;
            m0 = fmaxf(m0, fmaxf(C1[mf][nf][0], C1[mf][nf][1]));
            m1 = fmaxf(m1, fmaxf(C1[mf][nf][2], C1[mf][nf][3]));
        }
        #pragma unroll
        for (int o = 1; o < 4; o <<= 1) {
            m0 = fmaxf(m0, __shfl_xor_sync(0xffffffffu, m0, o));
            m1 = fmaxf(m1, __shfl_xor_sync(0xffffffffu, m1, o));
        }
        if (qt == 0) { sRM[r0 * 2 + wn1] = m0; sRM[(r0 + 8) * 2 + wn1] = m1; }
    }
    __syncthreads();
    #pragma unroll
    for (int mf = 0; mf < 2; mf++) {
        int r0 = wm1 * 32 + mf * 16 + g;
        float M0 = fmaxf(sRM[r0 * 2], sRM[r0 * 2 + 1]);
        float M1 = fmaxf(sRM[(r0 + 8) * 2], sRM[(r0 + 8) * 2 + 1]);
        float s0 = 0.f, s1 = 0.f;
        #pragma unroll
        for (int nf = 0; nf < 8; nf++) {
            C1[mf][nf][0] = __expf(C1[mf][nf][0] - M0);
            C1[mf][nf][1] = __expf(C1[mf][nf][1] - M0);
            C1[mf][nf][2] = __expf(C1[mf][nf][2] - M1);
            C1[mf][nf][3] = __expf(C1[mf][nf][3] - M1);
            s0 += C1[mf][nf][0] + C1[mf][nf][1];
            s1 += C1[mf][nf][2] + C1[mf][nf][3];
        }
        #pragma unroll
        for (int o = 1; o < 4; o <<= 1) {
            s0 += __shfl_xor_sync(0xffffffffu, s0, o);
            s1 += __shfl_xor_sync(0xffffffffu, s1, o);
        }
        if (qt == 0) {
            sRS[r0 * 2 + wn1] = s0; sRS[(r0 + 8) * 2 + wn1] = s1;
            if (wn1 == 0) {
                float rm0 = M0 + ssh[r0], rm1 = M1 + ssh[r0 + 8];
                g_rowmax[b * TT + t0 + r0]     = rm0;
                g_rowmax[b * TT + t0 + r0 + 8] = rm1;
                sBM[r0] = rm0; sBM[r0 + 8] = rm1;
            }
        }
    }
    __syncthreads();
    // normalize + pack probs fp16 into SA (pitch 272B)
    #pragma unroll
    for (int mf = 0; mf < 2; mf++) {
        int r0 = wm1 * 32 + mf * 16 + g;
        float inv0 = 1.f / (sRS[r0 * 2] + sRS[r0 * 2 + 1]);
        float inv1 = 1.f / (sRS[(r0 + 8) * 2] + sRS[(r0 + 8) * 2 + 1]);
        #pragma unroll
        for (int nf = 0; nf < 8; nf++) {
            int col = wn1 * 64 + nf * 8 + qt * 2;
            __half2 p0 = __floats2half2_rn(C1[mf][nf][0] * inv0, C1[mf][nf][1] * inv0);
            __half2 p1 = __floats2half2_rn(C1[mf][nf][2] * inv1, C1[mf][nf][3] * inv1);
            *(uint32_t*)(smem + SA + r0 * 272 + col * 2)       = *(uint32_t*)&p0;
            *(uint32_t*)(smem + SA + (r0 + 8) * 272 + col * 2) = *(uint32_t*)&p1;
        }
    }
    // warp 0: local max over the 128 rowmax values (for split-softmax partials)
    if (tid < 32) {
        float m = fmaxf(fmaxf(sBM[tid], sBM[tid + 32]), fmaxf(sBM[tid + 64], sBM[tid + 96]));
        #pragma unroll
        for (int o = 16; o; o >>= 1) m = fmaxf(m, __shfl_xor_sync(0xffffffffu, m, o));
        if (tid == 0) sLM[0] = m;
    }
    __syncthreads();

    // ================= GEMM2: C2Q[128t][256d] = P @ U (trans-B on U) =================
    const int wm2 = wid >> 2, wn2 = wid & 3;   // 2x4 warp grid, 64x64 tiles
    float C2[4][8][4];
    #pragma unroll
    for (int mf = 0; mf < 4; mf++)
        #pragma unroll
        for (int nf = 0; nf < 8; nf++)
            #pragma unroll
            for (int q = 0; q < 4; q++) C2[mf][nf][q] = 0.f;

    #pragma unroll
    for (int ks = 0; ks < 8; ks++) {
        uint32_t a[4][4];
        #pragma unroll
        for (int mf = 0; mf < 4; mf++) {
            uint32_t ar = sbase + SA + (uint32_t)((wm2 * 64 + mf * 16 + l16) * 272 + ks * 32 + lh * 16);
            ldsm4(a[mf], ar);
        }
        #pragma unroll
        for (int p = 0; p < 4; p++) {
            uint32_t br = sbase + SB + (uint32_t)((ks * 16 + l16) * 528
                                                  + (wn2 * 64 + p * 16 + lh * 8) * 2);
            uint32_t bb[4];
            ldsm4t(bb, br);
            uint32_t B0[2] = {bb[0], bb[1]}, B1[2] = {bb[2], bb[3]};
            #pragma unroll
            for (int mf = 0; mf < 4; mf++) {
                mma16816(C2[mf][2*p],   a[mf], B0);
                mma16816(C2[mf][2*p+1], a[mf], B1);
            }
        }
    }
    __syncthreads();   // SA+SB dead -> f32 epilogue buffer overlays from 0

    // ================= epilogue: G quarters 0,1,2 + partial Q2C =================
    {
        float* sEpi = (float*)smem;            // [128][264] f32
        #pragma unroll
        for (int mf = 0; mf < 4; mf++) {
            int r0 = wm2 * 64 + mf * 16 + g;
            #pragma unroll
            for (int nf = 0; nf < 8; nf++) {
                int c0 = wn2 * 64 + nf * 8 + qt * 2;
                *(float2*)&sEpi[r0 * 264 + c0]       = make_float2(C2[mf][nf][0], C2[mf][nf][1]);
                *(float2*)&sEpi[(r0 + 8) * 264 + c0] = make_float2(C2[mf][nf][2], C2[mf][nf][3]);
            }
        }
        __syncthreads();
        const float localM = sLM[0];
        float4 qa0 = make_float4(0.f, 0.f, 0.f, 0.f);
        float4 qa1 = make_float4(0.f, 0.f, 0.f, 0.f);
        #pragma unroll 2
        for (int r = 0; r < 16; r++) {
            int row = wid * 16 + r;
            float wgt = __expf(sBM[row] - localM);
            size_t rowg = (size_t)(b * TT + t0 + row);
            const float* Hrow = H + rowg * DD;
            float* Grow = G + rowg * (4 * DD);
            #pragma unroll
            for (int i = 0; i < 2; i++) {
                int d = lane * 4 + 128 * i;
                float4 cq = *(float4*)&sEpi[row * 264 + d];
                float4 h = *(const float4*)&Hrow[d];
                *(float4*)&Grow[d] = h;
                *(float4*)&Grow[DD + d] = cq;
                *(float4*)&Grow[2 * DD + d] = make_float4(h.x*cq.x, h.y*cq.y, h.z*cq.z, h.w*cq.w);
                if (i == 0) { qa0.x += wgt*h.x; qa0.y += wgt*h.y; qa0.z += wgt*h.z; qa0.w += wgt*h.w; }
                else        { qa1.x += wgt*h.x; qa1.y += wgt*h.y; qa1.z += wgt*h.z; qa1.w += wgt*h.w; }
            }
        }
        *(float4*)&sQ[wid * 256 + lane * 4]       = qa0;
        *(float4*)&sQ[wid * 256 + lane * 4 + 128] = qa1;
        __syncthreads();
        {
            float s = 0.f;
            #pragma unroll
            for (int w = 0; w < 8; w++) s += sQ[w * 256 + tid];
            g_q2cp[(size_t)(b * 8 + blockIdx.x) * DD + tid] = s;
        }
    }
}

// ---------------- Q2C reduce: recombine 8 split-softmax chunks per batch ----------------
__global__ void q2cr_kernel() {
    __shared__ float sM[8], sS[8];
    int b = blockIdx.x;
    int tid = threadIdx.x;
    int w = tid >> 5, lane = tid & 31;
    // warp w recomputes chunk-w max and sumexp from g_rowmax
    {
        float v[4], m = -1e30f;
        #pragma unroll
        for (int k = 0; k < 4; k++) {
            v[k] = g_rowmax[b * TT + w * 128 + lane + 32 * k];
            m = fmaxf(m, v[k]);
        }
        #pragma unroll
        for (int o = 16; o; o >>= 1) m = fmaxf(m, __shfl_xor_sync(0xffffffffu, m, o));
        float s = 0.f;
        #pragma unroll
        for (int k = 0; k < 4; k++) s += __expf(v[k] - m);
        #pragma unroll
        for (int o = 16; o; o >>= 1) s += __shfl_xor_sync(0xffffffffu, s, o);
        if (lane == 0) { sM[w] = m; sS[w] = s; }
    }
    __syncthreads();
    float Mg = sM[0];
    #pragma unroll
    for (int c = 1; c < 8; c++) Mg = fmaxf(Mg, sM[c]);
    float denom = 0.f, acc = 0.f;
    #pragma unroll
    for (int c = 0; c < 8; c++) {
        float sc = __expf(sM[c] - Mg);
        denom += sc * sS[c];
        acc   += sc * g_q2cp[(size_t)(b * 8 + c) * DD + tid];
    }
    g_q2c[b * DD + tid] = acc / denom;
}

// ---------------- G quarter 3 = H * Q2C ----------------
__global__ void g3_kernel(const float* __restrict__ H, float* __restrict__ G) {
    size_t base = (size_t)blockIdx.x * 1024 + threadIdx.x;
    #pragma unroll
    for (int k = 0; k < 4; k++) {
        size_t idx = base + 256 * k;           // float4 units
        int d4 = (int)(idx & 63);
        size_t bt = idx >> 6;
        int b = (int)(bt >> 10);
        float4 h = ((const float4*)H)[idx];
        float4 q = ((const float4*)g_q2c)[b * 64 + d4];
        float4 o = make_float4(h.x * q.x, h.y * q.y, h.z * q.z, h.w * q.w);
        ((float4*)G)[bt * 256 + 192 + d4] = o;
    }
}

extern "C" void kernel_launch(void* const* d_in, const int* in_sizes, int n_in,
                              void* d_out, int out_size) {
    const float* H    = (const float*)d_in[0];
    const float* U    = (const float*)d_in[1];
    const float* w_h  = (const float*)d_in[2];
    const float* w_u  = (const float*)d_in[3];
    const float* w_hu = (const float*)d_in[4];
    float* G = (float*)d_out;

    cudaFuncSetAttribute(bidaf_main, cudaFuncAttributeMaxDynamicSharedMemorySize, SMEM_TOTAL);

    usplit_kernel<<<BB * 2, 256>>>(U, w_u);
    bidaf_main<<<dim3(TT / TM, BB), 256, SMEM_TOTAL>>>(H, w_h, w_hu, G);
    q2cr_kernel<<<BB, 256>>>();
    g3_kernel<<<(BB * TT * DD / 4) / 1024, 256>>>(H, G);
}